// round 16
// baseline (speedup 1.0000x reference)
#include <cuda_runtime.h>
#include <cstdint>

// CTRNN scan — R14 champion + producer/consumer barrier split:
// warps 4-15 bar.arrive (non-blocking) and run ahead into step t+1's
// preamble (x stage + LDG + x-projection FMAs) while warps 0-3 run the
// epilogue; part[] ping-pongs on t&1 to close the overwrite hazard.
// Interleaved kpair/batch state, dual-k f32x2 register weights, combined
// count-2 mbarrier (7KB tx + local arrive), triple-buffered state,
// 2-deep x prefetch. B=64, T=4096, F=128, H=512, O=10, DT=0.1, fp32.

#define T_STEPS   4096
#define F_IN      128
#define H_DIM     512
#define O_OUT     10
#define CLUSTER_N 8
#define NCOL      64
#define NTHREADS  512
#define GRID      128
#define DT_C      0.1f
#define SLICE_BYTES  1024u                 // 32 rows x 32B (64 k x 4 b)
#define EXPECT_BYTES (7u * SLICE_BYTES)

typedef unsigned long long ull;

// state buffer: 256 rows x 32B; row j = kpair (2j,2j+1):
//   [ {s2j(b0),s2j+1(b0),s2j(b1),s2j+1(b1)} | {...b2,b3} ]
// rank r's slice = rows [32r,32r+32) = contiguous 1KB.
struct __align__(16) Smem {
    float  s[3][2048];           // 3 x 8KB
    float4 part[2][8][NCOL];     // ping-pong [t&1][kq][h] = {b0,b1,b2,b3}
    float  xq[2][512];           // 64 rows x 32B, same packing (f as k)
    ull    mbar[3];
};

__device__ __forceinline__ uint32_t smem_u32(const void* p) {
    uint32_t a;
    asm("{ .reg .u64 t; cvta.to.shared.u64 t, %1; cvt.u32.u64 %0, t; }"
        : "=r"(a) : "l"(p));
    return a;
}
__device__ __forceinline__ ull fma2(ull a, ull b, ull c) {
    ull d;
    asm("fma.rn.f32x2 %0, %1, %2, %3;" : "=l"(d) : "l"(a), "l"(b), "l"(c));
    return d;
}
__device__ __forceinline__ ull add2(ull a, ull b) {
    ull d;
    asm("add.rn.f32x2 %0, %1, %2;" : "=l"(d) : "l"(a), "l"(b));
    return d;
}
__device__ __forceinline__ ull packxy(float x, float y) {
    ull d;
    asm("mov.b64 %0, {%1, %2};" : "=l"(d) : "f"(x), "f"(y));
    return d;
}
__device__ __forceinline__ void unpack2(ull v, float& x, float& y) {
    asm("mov.b64 {%0, %1}, %2;" : "=f"(x), "=f"(y) : "l"(v));
}
__device__ __forceinline__ float tanh_fast(float x) {
    float y;
    asm("tanh.approx.f32 %0, %1;" : "=f"(y) : "f"(x));
    return y;
}
__device__ __forceinline__ void mbar_wait(uint32_t m, uint32_t ph) {
    uint32_t done;
    asm volatile(
        "{\n\t.reg .pred p;\n\t"
        "mbarrier.try_wait.parity.acquire.cta.shared::cta.b64 p, [%1], %2;\n\t"
        "selp.b32 %0, 1, 0, p;\n\t}"
        : "=r"(done) : "r"(m), "r"(ph) : "memory");
    while (!done) {
        asm volatile(
            "{\n\t.reg .pred p;\n\t"
            "mbarrier.try_wait.parity.acquire.cta.shared::cta.b64 p, [%1], %2, 0x989680;\n\t"
            "selp.b32 %0, 1, 0, p;\n\t}"
            : "=r"(done) : "r"(m), "r"(ph) : "memory");
    }
}
__device__ __forceinline__ void mbar_expect(uint32_t m) {
    asm volatile("mbarrier.arrive.expect_tx.shared::cta.b64 _, [%0], %1;"
                 :: "r"(m), "r"(EXPECT_BYTES) : "memory");
}
__device__ __forceinline__ void mbar_arrive(uint32_t m) {
    asm volatile("mbarrier.arrive.release.cta.shared::cta.b64 _, [%0];"
                 :: "r"(m) : "memory");
}
__device__ __forceinline__ uint32_t mapa_u32(uint32_t la, uint32_t r) {
    uint32_t ra;
    asm("mapa.shared::cluster.u32 %0, %1, %2;" : "=r"(ra) : "r"(la), "r"(r));
    return ra;
}
__device__ __forceinline__ void bulk_copy_peer(uint32_t dst, uint32_t src,
                                               uint32_t bytes, uint32_t rmbar) {
    asm volatile(
        "cp.async.bulk.shared::cluster.shared::cta.mbarrier::complete_tx::bytes "
        "[%0], [%1], %2, [%3];"
        :: "r"(dst), "r"(src), "r"(bytes), "r"(rmbar) : "memory");
}

__global__ void __cluster_dims__(CLUSTER_N, 1, 1) __launch_bounds__(NTHREADS, 1)
ctrnn_scan(const float* __restrict__ xg,   const float* __restrict__ ic,
           const float* __restrict__ Wing, const float* __restrict__ Wrecg,
           const float* __restrict__ bg,   const float* __restrict__ taug,
           const float* __restrict__ Rw,   const float* __restrict__ Rb,
           float* __restrict__ outg)
{
    __shared__ Smem sm;

    uint32_t rank;
    asm("mov.u32 %0, %%cluster_ctarank;" : "=r"(rank));
    const int tid = threadIdx.x;
    const int cl  = blockIdx.x / CLUSTER_N;
    const int c0  = (int)rank * NCOL;
    const int gb0 = cl * 4;

    const int h  = tid & 63;    // output column within slice
    const int kq = tid >> 6;    // k-subgroup: k = src*64 + kq*8 + (0..7)

    // ---- weights to registers: dual-k packed, per-src groups ----
    ull wr[32];
    #pragma unroll
    for (int i = 0; i < 32; i++) {
        const int src = i >> 2, m = i & 3;
        const int k0 = src * 64 + kq * 8 + 2 * m;
        wr[i] = packxy(Wrecg[k0 * H_DIM + c0 + h],
                       Wrecg[(k0 + 1) * H_DIM + c0 + h]);
    }
    ull wi[8];
    #pragma unroll
    for (int m = 0; m < 8; m++) {
        const int f0 = kq * 16 + 2 * m;
        wi[m] = packxy(Wing[f0 * H_DIM + c0 + h],
                       Wing[(f0 + 1) * H_DIM + c0 + h]);
    }

    // ---- epilogue params (tid<128, warps 0-3) ----
    const int eh = tid & 63, ebp = (tid >> 6) & 1;
    float biasv = 0.f, arv = 0.f, sA = 0.f, sB = 0.f;
    if (tid < 128) {
        biasv = bg[c0 + eh];
        arv   = DT_C / taug[c0 + eh];
        sA = sB = ic[c0 + eh];
    }

    // ---- init: state buf0 (interleaved layout), x[0], mbarriers ----
    for (int i = tid; i < 2048; i += NTHREADS)
        sm.s[0][i] = ic[(i >> 3) * 2 + (i & 1)];
    const int xb = tid >> 7, xf = tid & 127;
    const uint32_t xoff = (uint32_t)((xf >> 1) * 32 + (xb >> 1) * 16
                                     + (xb & 1) * 8 + (xf & 1) * 4);
    sm.xq[0][xoff >> 2] = xg[(ull)(gb0 + xb) * T_STEPS * F_IN + xf];

    const uint32_t mbase = smem_u32(&sm.mbar[0]);
    const uint32_t sbase = smem_u32(&sm.s[0][0]);
    if (tid == 0) {
        #pragma unroll
        for (int i = 0; i < 3; i++)
            asm volatile("mbarrier.init.shared::cta.b64 [%0], %1;"
                         :: "r"(mbase + i * 8u), "r"(2) : "memory");
        #pragma unroll
        for (int i = 0; i < 3; i++) mbar_expect(mbase + i * 8u);
    }
    __syncthreads();
    asm volatile("barrier.cluster.arrive.aligned;" ::: "memory");
    asm volatile("barrier.cluster.wait.aligned;"   ::: "memory");

    const float* xsrc = xg + (ull)(gb0 + xb) * T_STEPS * F_IN + xf;

    // 2-deep x pipeline: px_stage holds x[t+1] (loaded a full step ago)
    float px_stage = xsrc[F_IN];   // x[1]

    for (int t = 0; t < T_STEPS; t++) {
        const int cur  = t % 3;
        const int nbuf = (t + 1) % 3;
        const int cx   = t & 1;

        // stage x[t+1] (value loaded at step t-1)
        if (t + 1 < T_STEPS) sm.xq[cx ^ 1][xoff >> 2] = px_stage;

        // issue LDG for x[t+2]: a full step of latency cover
        float px_next = 0.f;
        if (t + 2 < T_STEPS) px_next = xsrc[(ull)(t + 2) * F_IN];

        // ---- x-projection FMAs: independent of s(t) ----
        ull a0 = 0, a1 = 0, a2 = 0, a3 = 0;
        {
            const char* xp = (const char*)&sm.xq[cx][0] + kq * 256;
            #pragma unroll
            for (int m = 0; m < 8; m++) {
                const double2 v0 = *(const double2*)(xp + m * 32);
                const double2 v1 = *(const double2*)(xp + m * 32 + 16);
                a0 = fma2(wi[m], __double_as_longlong(v0.x), a0);
                a1 = fma2(wi[m], __double_as_longlong(v0.y), a1);
                a2 = fma2(wi[m], __double_as_longlong(v1.x), a2);
                a3 = fma2(wi[m], __double_as_longlong(v1.y), a3);
            }
        }

        // ---- single combined wait: 7 peer slices (tx) + own (arrive) ----
        if (t > 0) {
            const uint32_t m = mbase + (uint32_t)cur * 8u;
            mbar_wait(m, (((uint32_t)t - 1u) / 3u) & 1u);
            if (tid == 0) mbar_expect(m);    // re-arm for step t+3
        }

        // ---- recurrent FMAs: 8 srcs x 4 kpairs, mov-free ----
        {
            const char* sp = (const char*)&sm.s[cur][0] + kq * 128;
            #pragma unroll
            for (int i = 0; i < 32; i++) {
                const int src = i >> 2, m = i & 3;
                const char* rp = sp + src * 1024 + m * 32;
                const double2 v0 = *(const double2*)(rp);
                const double2 v1 = *(const double2*)(rp + 16);
                a0 = fma2(wr[i], __double_as_longlong(v0.x), a0);
                a1 = fma2(wr[i], __double_as_longlong(v0.y), a1);
                a2 = fma2(wr[i], __double_as_longlong(v1.x), a2);
                a3 = fma2(wr[i], __double_as_longlong(v1.y), a3);
            }
        }

        // horizontal add (even/odd k), single STS.128, ping-pong buffer
        {
            float e, o, f0, f1, f2, f3;
            unpack2(a0, e, o); f0 = e + o;
            unpack2(a1, e, o); f1 = e + o;
            unpack2(a2, e, o); f2 = e + o;
            unpack2(a3, e, o); f3 = e + o;
            sm.part[cx][kq][h] = make_float4(f0, f1, f2, f3);
        }

        px_stage = px_next;   // rotate x pipeline

        // ---- split barrier: producers release & run ahead ----
        if (tid >= 128) {
            asm volatile("bar.arrive 1, %0;" :: "n"(NTHREADS) : "memory");
            continue;   // straight into step t+1 preamble, then mbar wait
        }
        asm volatile("bar.sync 1, %0;" :: "n"(NTHREADS) : "memory");

        // ---- epilogue: warps 0-3 only ----
        {
            ull s8 = __double_as_longlong(
                *(const double*)((const char*)&sm.part[cx][0][eh] + ebp * 8));
            #pragma unroll
            for (int q = 1; q < 8; q++)
                s8 = add2(s8, __double_as_longlong(
                    *(const double*)((const char*)&sm.part[cx][q][eh] + ebp * 8)));
            float pA, pB;
            unpack2(s8, pA, pB);
            const float nA = fmaf(arv, tanh_fast(pA + biasv) - sA, sA);
            const float nB = fmaf(arv, tanh_fast(pB + biasv) - sB, sB);
            sA = nA; sB = nB;
            const int k = c0 + eh;
            float* dst = (float*)((char*)&sm.s[nbuf][0]
                        + (k >> 1) * 32 + ebp * 16 + (k & 1) * 4);
            dst[0] = nA;
            dst[2] = nB;

            asm volatile("bar.sync 2, 128;" ::: "memory");

            if (tid < 8) {
                const uint32_t src = sbase + (uint32_t)nbuf * 8192u
                                   + rank * SLICE_BYTES;
                const uint32_t rmb = mbase + (uint32_t)nbuf * 8u;
                if (tid < 7) {
                    asm volatile("fence.proxy.async.shared::cta;" ::: "memory");
                    const uint32_t peer = (uint32_t)tid
                                        + ((uint32_t)tid >= rank ? 1u : 0u);
                    bulk_copy_peer(mapa_u32(src, peer), src, SLICE_BYTES,
                                   mapa_u32(rmb, peer));
                } else {
                    mbar_arrive(rmb);   // own slice release
                }
            }
        }
    }

    // ---- final wait + readout ----
    mbar_wait(mbase + (uint32_t)(T_STEPS % 3) * 8u,
              (((uint32_t)T_STEPS - 1u) / 3u) & 1u);
    __syncthreads();

    if (rank == 0) {
        const float* sf = &sm.s[T_STEPS % 3][0];
        const int wid_ = tid >> 5, lane = tid & 31;
        for (int bo = wid_; bo < 4 * O_OUT; bo += NTHREADS / 32) {
            const int b = bo / O_OUT, o = bo % O_OUT;
            float acc = 0.f;
            for (int k = lane; k < H_DIM; k += 32)
                acc += sf[(k >> 1) * 8 + (b >> 1) * 4 + (b & 1) * 2 + (k & 1)]
                     * Rw[k * O_OUT + o];
            #pragma unroll
            for (int off = 16; off; off >>= 1)
                acc += __shfl_xor_sync(0xffffffffu, acc, off);
            if (lane == 0) outg[(gb0 + b) * O_OUT + o] = acc + Rb[o];
        }
    }

    // exit safety: peer copies may still target this CTA's SMEM
    asm volatile("barrier.cluster.arrive.aligned;" ::: "memory");
    asm volatile("barrier.cluster.wait.aligned;"   ::: "memory");
}

extern "C" void kernel_launch(void* const* d_in, const int* in_sizes, int n_in,
                              void* d_out, int out_size)
{
    const float* x    = (const float*)d_in[0];
    const float* ic   = (const float*)d_in[1];
    const float* Win  = (const float*)d_in[2];
    const float* Wrec = (const float*)d_in[3];
    const float* b    = (const float*)d_in[4];
    const float* tau  = (const float*)d_in[5];
    const float* Rw   = (const float*)d_in[6];
    const float* Rb   = (const float*)d_in[7];
    float* out = (float*)d_out;
    (void)in_sizes; (void)n_in; (void)out_size;

    ctrnn_scan<<<GRID, NTHREADS>>>(x, ic, Win, Wrec, b, tau, Rw, Rb, out);
}

// round 17
// speedup vs baseline: 1.7256x; 1.7256x over previous
#include <cuda_runtime.h>
#include <cstdint>

// CTRNN scan — R14 champion + epilogue tree-reduce + own-partial register
// reuse. Interleaved kpair/batch state, dual-k f32x2 register weights,
// combined count-2 mbarrier (7KB tx + local arrive), triple-buffered
// state, 2-deep x prefetch. B=64, T=4096, F=128, H=512, O=10, DT=0.1, fp32.

#define T_STEPS   4096
#define F_IN      128
#define H_DIM     512
#define O_OUT     10
#define CLUSTER_N 8
#define NCOL      64
#define NTHREADS  512
#define GRID      128
#define DT_C      0.1f
#define SLICE_BYTES  1024u                 // 32 rows x 32B (64 k x 4 b)
#define EXPECT_BYTES (7u * SLICE_BYTES)

typedef unsigned long long ull;

// state buffer: 256 rows x 32B; row j = kpair (2j,2j+1):
//   [ {s2j(b0),s2j+1(b0),s2j(b1),s2j+1(b1)} | {...b2,b3} ]
// rank r's slice = rows [32r,32r+32) = contiguous 1KB.
struct __align__(16) Smem {
    float  s[3][2048];           // 3 x 8KB
    double part[8][2][NCOL];     // [kq][bpair][h] = {b_even, b_odd}
    float  xq[2][512];           // 64 rows x 32B, same packing (f as k)
    ull    mbar[3];
};

__device__ __forceinline__ uint32_t smem_u32(const void* p) {
    uint32_t a;
    asm("{ .reg .u64 t; cvta.to.shared.u64 t, %1; cvt.u32.u64 %0, t; }"
        : "=r"(a) : "l"(p));
    return a;
}
__device__ __forceinline__ ull fma2(ull a, ull b, ull c) {
    ull d;
    asm("fma.rn.f32x2 %0, %1, %2, %3;" : "=l"(d) : "l"(a), "l"(b), "l"(c));
    return d;
}
__device__ __forceinline__ ull add2(ull a, ull b) {
    ull d;
    asm("add.rn.f32x2 %0, %1, %2;" : "=l"(d) : "l"(a), "l"(b));
    return d;
}
__device__ __forceinline__ ull packxy(float x, float y) {
    ull d;
    asm("mov.b64 %0, {%1, %2};" : "=l"(d) : "f"(x), "f"(y));
    return d;
}
__device__ __forceinline__ void unpack2(ull v, float& x, float& y) {
    asm("mov.b64 {%0, %1}, %2;" : "=f"(x), "=f"(y) : "l"(v));
}
__device__ __forceinline__ float tanh_fast(float x) {
    float y;
    asm("tanh.approx.f32 %0, %1;" : "=f"(y) : "f"(x));
    return y;
}
__device__ __forceinline__ void mbar_wait(uint32_t m, uint32_t ph) {
    uint32_t done;
    asm volatile(
        "{\n\t.reg .pred p;\n\t"
        "mbarrier.try_wait.parity.acquire.cta.shared::cta.b64 p, [%1], %2;\n\t"
        "selp.b32 %0, 1, 0, p;\n\t}"
        : "=r"(done) : "r"(m), "r"(ph) : "memory");
    while (!done) {
        asm volatile(
            "{\n\t.reg .pred p;\n\t"
            "mbarrier.try_wait.parity.acquire.cta.shared::cta.b64 p, [%1], %2, 0x989680;\n\t"
            "selp.b32 %0, 1, 0, p;\n\t}"
            : "=r"(done) : "r"(m), "r"(ph) : "memory");
    }
}
__device__ __forceinline__ void mbar_expect(uint32_t m) {
    asm volatile("mbarrier.arrive.expect_tx.shared::cta.b64 _, [%0], %1;"
                 :: "r"(m), "r"(EXPECT_BYTES) : "memory");
}
__device__ __forceinline__ void mbar_arrive(uint32_t m) {
    asm volatile("mbarrier.arrive.release.cta.shared::cta.b64 _, [%0];"
                 :: "r"(m) : "memory");
}
__device__ __forceinline__ uint32_t mapa_u32(uint32_t la, uint32_t r) {
    uint32_t ra;
    asm("mapa.shared::cluster.u32 %0, %1, %2;" : "=r"(ra) : "r"(la), "r"(r));
    return ra;
}
__device__ __forceinline__ void bulk_copy_peer(uint32_t dst, uint32_t src,
                                               uint32_t bytes, uint32_t rmbar) {
    asm volatile(
        "cp.async.bulk.shared::cluster.shared::cta.mbarrier::complete_tx::bytes "
        "[%0], [%1], %2, [%3];"
        :: "r"(dst), "r"(src), "r"(bytes), "r"(rmbar) : "memory");
}

__global__ void __cluster_dims__(CLUSTER_N, 1, 1) __launch_bounds__(NTHREADS, 1)
ctrnn_scan(const float* __restrict__ xg,   const float* __restrict__ ic,
           const float* __restrict__ Wing, const float* __restrict__ Wrecg,
           const float* __restrict__ bg,   const float* __restrict__ taug,
           const float* __restrict__ Rw,   const float* __restrict__ Rb,
           float* __restrict__ outg)
{
    __shared__ Smem sm;

    uint32_t rank;
    asm("mov.u32 %0, %%cluster_ctarank;" : "=r"(rank));
    const int tid = threadIdx.x;
    const int cl  = blockIdx.x / CLUSTER_N;
    const int c0  = (int)rank * NCOL;
    const int gb0 = cl * 4;

    const int h  = tid & 63;    // output column within slice
    const int kq = tid >> 6;    // k-subgroup: k = src*64 + kq*8 + (0..7)

    // ---- weights to registers: dual-k packed, per-src groups ----
    ull wr[32];
    #pragma unroll
    for (int i = 0; i < 32; i++) {
        const int src = i >> 2, m = i & 3;
        const int k0 = src * 64 + kq * 8 + 2 * m;
        wr[i] = packxy(Wrecg[k0 * H_DIM + c0 + h],
                       Wrecg[(k0 + 1) * H_DIM + c0 + h]);
    }
    ull wi[8];
    #pragma unroll
    for (int m = 0; m < 8; m++) {
        const int f0 = kq * 16 + 2 * m;
        wi[m] = packxy(Wing[f0 * H_DIM + c0 + h],
                       Wing[(f0 + 1) * H_DIM + c0 + h]);
    }

    // ---- epilogue params (tid<128; kq==ebp there: 0 or 1) ----
    const int eh = tid & 63, ebp = (tid >> 6) & 1;
    float biasv = 0.f, arv = 0.f, sA = 0.f, sB = 0.f;
    if (tid < 128) {
        biasv = bg[c0 + eh];
        arv   = DT_C / taug[c0 + eh];
        sA = sB = ic[c0 + eh];
    }

    // ---- init: state buf0 (interleaved layout), x[0], mbarriers ----
    for (int i = tid; i < 2048; i += NTHREADS)
        sm.s[0][i] = ic[(i >> 3) * 2 + (i & 1)];
    const int xb = tid >> 7, xf = tid & 127;
    const uint32_t xoff = (uint32_t)((xf >> 1) * 32 + (xb >> 1) * 16
                                     + (xb & 1) * 8 + (xf & 1) * 4);
    sm.xq[0][xoff >> 2] = xg[(ull)(gb0 + xb) * T_STEPS * F_IN + xf];

    const uint32_t mbase = smem_u32(&sm.mbar[0]);
    const uint32_t sbase = smem_u32(&sm.s[0][0]);
    if (tid == 0) {
        #pragma unroll
        for (int i = 0; i < 3; i++)
            asm volatile("mbarrier.init.shared::cta.b64 [%0], %1;"
                         :: "r"(mbase + i * 8u), "r"(2) : "memory");
        #pragma unroll
        for (int i = 0; i < 3; i++) mbar_expect(mbase + i * 8u);
    }
    __syncthreads();
    asm volatile("barrier.cluster.arrive.aligned;" ::: "memory");
    asm volatile("barrier.cluster.wait.aligned;"   ::: "memory");

    const float* xsrc = xg + (ull)(gb0 + xb) * T_STEPS * F_IN + xf;

    // 2-deep x pipeline: px_stage holds x[t+1] (loaded a full step ago)
    float px_stage = xsrc[F_IN];   // x[1]

    for (int t = 0; t < T_STEPS; t++) {
        const int cur  = t % 3;
        const int nbuf = (t + 1) % 3;
        const int cx   = t & 1;

        // stage x[t+1] (value loaded at step t-1)
        if (t + 1 < T_STEPS) sm.xq[cx ^ 1][xoff >> 2] = px_stage;

        // issue LDG for x[t+2]: a full step of latency cover
        float px_next = 0.f;
        if (t + 2 < T_STEPS) px_next = xsrc[(ull)(t + 2) * F_IN];

        // ---- x-projection FMAs: independent of s(t) ----
        ull a0 = 0, a1 = 0, a2 = 0, a3 = 0;
        {
            const char* xp = (const char*)&sm.xq[cx][0] + kq * 256;
            #pragma unroll
            for (int m = 0; m < 8; m++) {
                const double2 v0 = *(const double2*)(xp + m * 32);
                const double2 v1 = *(const double2*)(xp + m * 32 + 16);
                a0 = fma2(wi[m], __double_as_longlong(v0.x), a0);
                a1 = fma2(wi[m], __double_as_longlong(v0.y), a1);
                a2 = fma2(wi[m], __double_as_longlong(v1.x), a2);
                a3 = fma2(wi[m], __double_as_longlong(v1.y), a3);
            }
        }

        // ---- single combined wait: 7 peer slices (tx) + own (arrive) ----
        if (t > 0) {
            const uint32_t m = mbase + (uint32_t)cur * 8u;
            mbar_wait(m, (((uint32_t)t - 1u) / 3u) & 1u);
            if (tid == 0) mbar_expect(m);    // re-arm for step t+3
        }

        // ---- recurrent FMAs: 8 srcs x 4 kpairs, mov-free ----
        {
            const char* sp = (const char*)&sm.s[cur][0] + kq * 128;
            #pragma unroll
            for (int i = 0; i < 32; i++) {
                const int src = i >> 2, m = i & 3;
                const char* rp = sp + src * 1024 + m * 32;
                const double2 v0 = *(const double2*)(rp);
                const double2 v1 = *(const double2*)(rp + 16);
                a0 = fma2(wr[i], __double_as_longlong(v0.x), a0);
                a1 = fma2(wr[i], __double_as_longlong(v0.y), a1);
                a2 = fma2(wr[i], __double_as_longlong(v1.x), a2);
                a3 = fma2(wr[i], __double_as_longlong(v1.y), a3);
            }
        }

        // horizontal add (even/odd k) and store partials; keep this
        // thread's own (column, bpair) partial live in a register
        ull ownp = 0ull;
        {
            float e, o, f0, f1, f2, f3;
            unpack2(a0, e, o); f0 = e + o;
            unpack2(a1, e, o); f1 = e + o;
            unpack2(a2, e, o); f2 = e + o;
            unpack2(a3, e, o); f3 = e + o;
            const ull pEv = packxy(f0, f1);   // bpair 0 (b0,b1)
            const ull pOd = packxy(f2, f3);   // bpair 1 (b2,b3)
            sm.part[kq][0][h] = __longlong_as_double(pEv);
            sm.part[kq][1][h] = __longlong_as_double(pOd);
            // epilogue thread (tid<128) has kq==ebp: its own slot is
            // part[kq][ebp][eh] = (kq==0 ? pEv : pOd)
            ownp = (kq == 0) ? pEv : pOd;
        }

        px_stage = px_next;   // rotate x pipeline

        __syncthreads();   // partials + staged x visible

        // ---- epilogue: 4 warps; 7 loads + own register, tree add ----
        if (tid < 128) {
            // load the 7 partials with q != kq (kq==ebp here)
            ull p[7];
            #pragma unroll
            for (int j = 0; j < 7; j++) {
                const int q = j + (j >= ebp ? 1 : 0);   // skip q==kq
                p[j] = __double_as_longlong(sm.part[q][ebp][eh]);
            }
            const ull s8 = add2(add2(add2(p[0], p[1]), add2(p[2], p[3])),
                                add2(add2(p[4], p[5]), add2(p[6], ownp)));
            float pA, pB;
            unpack2(s8, pA, pB);
            const float nA = fmaf(arv, tanh_fast(pA + biasv) - sA, sA);
            const float nB = fmaf(arv, tanh_fast(pB + biasv) - sB, sB);
            sA = nA; sB = nB;
            const int k = c0 + eh;
            float* dst = (float*)((char*)&sm.s[nbuf][0]
                        + (k >> 1) * 32 + ebp * 16 + (k & 1) * 4);
            dst[0] = nA;
            dst[2] = nB;

            asm volatile("bar.sync 1, 128;" ::: "memory");

            if (tid < 8) {
                const uint32_t src = sbase + (uint32_t)nbuf * 8192u
                                   + rank * SLICE_BYTES;
                const uint32_t rmb = mbase + (uint32_t)nbuf * 8u;
                if (tid < 7) {
                    asm volatile("fence.proxy.async.shared::cta;" ::: "memory");
                    const uint32_t peer = (uint32_t)tid
                                        + ((uint32_t)tid >= rank ? 1u : 0u);
                    bulk_copy_peer(mapa_u32(src, peer), src, SLICE_BYTES,
                                   mapa_u32(rmb, peer));
                } else {
                    mbar_arrive(rmb);   // own slice release
                }
            }
        }
    }

    // ---- final wait + readout ----
    mbar_wait(mbase + (uint32_t)(T_STEPS % 3) * 8u,
              (((uint32_t)T_STEPS - 1u) / 3u) & 1u);
    __syncthreads();

    if (rank == 0) {
        const float* sf = &sm.s[T_STEPS % 3][0];
        const int wid_ = tid >> 5, lane = tid & 31;
        for (int bo = wid_; bo < 4 * O_OUT; bo += NTHREADS / 32) {
            const int b = bo / O_OUT, o = bo % O_OUT;
            float acc = 0.f;
            for (int k = lane; k < H_DIM; k += 32)
                acc += sf[(k >> 1) * 8 + (b >> 1) * 4 + (b & 1) * 2 + (k & 1)]
                     * Rw[k * O_OUT + o];
            #pragma unroll
            for (int off = 16; off; off >>= 1)
                acc += __shfl_xor_sync(0xffffffffu, acc, off);
            if (lane == 0) outg[(gb0 + b) * O_OUT + o] = acc + Rb[o];
        }
    }

    // exit safety: peer copies may still target this CTA's SMEM
    asm volatile("barrier.cluster.arrive.aligned;" ::: "memory");
    asm volatile("barrier.cluster.wait.aligned;"   ::: "memory");
}

extern "C" void kernel_launch(void* const* d_in, const int* in_sizes, int n_in,
                              void* d_out, int out_size)
{
    const float* x    = (const float*)d_in[0];
    const float* ic   = (const float*)d_in[1];
    const float* Win  = (const float*)d_in[2];
    const float* Wrec = (const float*)d_in[3];
    const float* b    = (const float*)d_in[4];
    const float* tau  = (const float*)d_in[5];
    const float* Rw   = (const float*)d_in[6];
    const float* Rb   = (const float*)d_in[7];
    float* out = (float*)d_out;
    (void)in_sizes; (void)n_in; (void)out_size;

    ctrnn_scan<<<GRID, NTHREADS>>>(x, ic, Win, Wrec, b, tau, Rw, Rb, out);
}